// round 16
// baseline (speedup 1.0000x reference)
#include <cuda_runtime.h>
#include <cuda_bf16.h>
#include <cuda_fp16.h>
#include <math.h>
#include <stdint.h>

#define B_   4
#define S_   2048
#define H_   16
#define DH_  64
#define D_   1024
#define FF_  2048
#define BS_  (B_*S_)
#define BH_  (B_*H_)

// ---------------- scratch (device globals; no runtime allocation) -----------
__device__ float  g_qkv[(size_t)BS_ * 3 * D_];
__device__ __half g_qi [(size_t)BS_ * D_];
__device__ __half g_wq [(size_t)D_ * 3 * D_];
__device__ __half g_w1 [(size_t)D_ * FF_];
__device__ __half g_w2 [(size_t)FF_ * D_];
__device__ __half g_qf [(size_t)BH_ * S_ * DH_];
__device__ __half g_kf [(size_t)BH_ * S_ * DH_];
__device__ __half g_vf [(size_t)BH_ * S_ * DH_];
__device__ float  g_att[(size_t)BS_ * D_];
__device__ float  g_x  [(size_t)BS_ * D_];
__device__ __half g_xh [(size_t)BS_ * D_];
__device__ __half g_hh [(size_t)BS_ * FF_];

// ---------------- helpers ------------------------------------------------------
__device__ __forceinline__ unsigned packhf(float a, float b) {
    __half2 t = __floats2half2_rn(a, b);
    return *reinterpret_cast<unsigned*>(&t);
}

// ---------------- PTX primitives ---------------------------------------------
__device__ __forceinline__ void ldsm4(unsigned* d, unsigned a) {
    asm volatile("ldmatrix.sync.aligned.m8n8.x4.shared.b16 {%0,%1,%2,%3}, [%4];"
                 : "=r"(d[0]), "=r"(d[1]), "=r"(d[2]), "=r"(d[3]) : "r"(a));
}
__device__ __forceinline__ void ldsm4t(unsigned* d, unsigned a) {
    asm volatile("ldmatrix.sync.aligned.m8n8.x4.trans.shared.b16 {%0,%1,%2,%3}, [%4];"
                 : "=r"(d[0]), "=r"(d[1]), "=r"(d[2]), "=r"(d[3]) : "r"(a));
}
__device__ __forceinline__ void mma_f16(float* c, const unsigned* a,
                                        unsigned b0, unsigned b1) {
    asm volatile(
        "mma.sync.aligned.m16n8k16.row.col.f32.f16.f16.f32 "
        "{%0,%1,%2,%3}, {%4,%5,%6,%7}, {%8,%9}, {%0,%1,%2,%3};"
        : "+f"(c[0]), "+f"(c[1]), "+f"(c[2]), "+f"(c[3])
        : "r"(a[0]), "r"(a[1]), "r"(a[2]), "r"(a[3]), "r"(b0), "r"(b1));
}
__device__ __forceinline__ void cpa16(unsigned dst, const void* src) {
    asm volatile("cp.async.ca.shared.global [%0], [%1], 16;" :: "r"(dst), "l"(src));
}
__device__ __forceinline__ void cpa_commit() {
    asm volatile("cp.async.commit_group;");
}
__device__ __forceinline__ void cpa_wait0() {
    asm volatile("cp.async.wait_group 0;" ::: "memory");
}

// ============================================================================
// fused convert: all fp32->fp16 planes in one launch (grid-stride, segmented)
// ============================================================================
__global__ __launch_bounds__(256) void hsplit_all(
    const float* __restrict__ A0, __half* __restrict__ O0, int n0,
    const float* __restrict__ A1, __half* __restrict__ O1, int n1,
    const float* __restrict__ A2, __half* __restrict__ O2, int n2,
    const float* __restrict__ A3, __half* __restrict__ O3, int n3)
{
    const int stride = gridDim.x * blockDim.x;
    const int total = n0 + n1 + n2 + n3;
    for (int i = blockIdx.x * blockDim.x + threadIdx.x; i < total; i += stride) {
        const float* src;
        __half* dst;
        int j = i;
        if (j < n0) { src = A0; dst = O0; }
        else if ((j -= n0) < n1) { src = A1; dst = O1; }
        else if ((j -= n1) < n2) { src = A2; dst = O2; }
        else { j -= n2; src = A3; dst = O3; }
        float4 v = ((const float4*)src)[j];
        ((uint2*)dst)[j] = make_uint2(packhf(v.x, v.y), packhf(v.z, v.w));
    }
}

// ============================================================================
// Raw-mma fp16 GEMM, k-chunk 64, cp.async double-buffer, 1 sync/chunk.
// CTA 128x128, 4 warps (2m x 2n), warp tile 64x64.
// MODE 0: C fp32.  MODE 1: SiLU -> Ch fp16.  MODE 2: +res -> C fp32.
// Buffer: A[128][72h] 18432 B | B[64][136h] 17408 B => 35840/buffer.
// ============================================================================
#define GA_ 144
#define GB_ 272
#define GBUF 35840
#define GEMM_SMEM (2 * GBUF)

template <int MODE>
__global__ __launch_bounds__(128, 2) void mma_gemm(
    const __half* __restrict__ Ah, const __half* __restrict__ Bh,
    const float* __restrict__ bias, const float* __restrict__ res,
    float* __restrict__ C, __half* __restrict__ Ch,
    int M, int N, int K)
{
    extern __shared__ unsigned char smg[];
    const unsigned sb = (unsigned)__cvta_generic_to_shared(smg);

    const int tid = threadIdx.x;
    const int w = tid >> 5;
    const int lane = tid & 31;
    const int wmr = w >> 1;
    const int wnc = w & 1;
    const int bx = blockIdx.x, by = blockIdx.y;

    const int lj = lane >> 3, lr = lane & 7;
    const int rowoff = (lj & 1) * 8 + lr;
    const int coloff = (lj >> 1) * 8;
    const int g = lane >> 2, c2 = (lane & 3) * 2;

    float acc[4][8][4];
    #pragma unroll
    for (int mt = 0; mt < 4; mt++)
        #pragma unroll
        for (int n = 0; n < 8; n++) {
            acc[mt][n][0] = 0.f; acc[mt][n][1] = 0.f;
            acc[mt][n][2] = 0.f; acc[mt][n][3] = 0.f;
        }

    const int NC = K >> 6;

    // staging: 2048 16B-chunks per buffer, 16 per thread
    auto stage = [&](int kc, unsigned bufo) {
        const int k0 = kc * 64;
        #pragma unroll
        for (int i = 0; i < 16; i++) {
            int chunk = i * 128 + tid;
            if (chunk < 1024) {
                int row = chunk >> 3;
                int q = chunk & 7;
                const __half* src = Ah + (size_t)(by * 128 + row) * K + k0 + q * 8;
                cpa16(sb + bufo + row * GA_ + q * 16, src);
            } else {
                int c = chunk - 1024;
                int row = c >> 4;
                int o = c & 15;
                const __half* src = Bh + (size_t)(k0 + row) * N + bx * 128 + o * 8;
                cpa16(sb + bufo + 18432u + row * GB_ + o * 16, src);
            }
        }
    };

    stage(0, 0u);
    cpa_commit();

    for (int kc = 0; kc < NC; kc++) {
        cpa_wait0();
        __syncthreads();

        const unsigned buf = (unsigned)((kc & 1) * GBUF);
        if (kc + 1 < NC) {
            stage(kc + 1, (unsigned)(((kc + 1) & 1) * GBUF));
            cpa_commit();
        }

        const unsigned uA = sb + buf, uB = sb + buf + 18432u;

        #pragma unroll
        for (int ks = 0; ks < 4; ks++) {
            unsigned ah[4][4];
            #pragma unroll
            for (int mt = 0; mt < 4; mt++) {
                const unsigned addr = uA
                    + (unsigned)((wmr * 64 + mt * 16 + rowoff) * GA_ + (ks * 16 + coloff) * 2);
                ldsm4(ah[mt], addr);
            }
            #pragma unroll
            for (int gg = 0; gg < 4; gg++) {
                unsigned bf[4];
                const unsigned baddr = uB
                    + (unsigned)((ks * 16 + rowoff) * GB_ + (wnc * 64 + gg * 16 + coloff) * 2);
                ldsm4t(bf, baddr);
                #pragma unroll
                for (int mt = 0; mt < 4; mt++) {
                    mma_f16(acc[mt][2 * gg],     ah[mt], bf[0], bf[1]);
                    mma_f16(acc[mt][2 * gg + 1], ah[mt], bf[2], bf[3]);
                }
            }
        }
    }

    #pragma unroll
    for (int mt = 0; mt < 4; mt++) {
        #pragma unroll
        for (int n = 0; n < 8; n++) {
            const int row = by * 128 + wmr * 64 + mt * 16 + g;
            const int col = bx * 128 + wnc * 64 + n * 8 + c2;
            float2 bb2 = *(const float2*)(bias + col);
            float v0 = acc[mt][n][0] + bb2.x;
            float v1 = acc[mt][n][1] + bb2.y;
            float v2 = acc[mt][n][2] + bb2.x;
            float v3 = acc[mt][n][3] + bb2.y;
            if (MODE == 1) {
                v0 = v0 / (1.f + __expf(-v0));
                v1 = v1 / (1.f + __expf(-v1));
                v2 = v2 / (1.f + __expf(-v2));
                v3 = v3 / (1.f + __expf(-v3));
                *(unsigned*)(Ch + (size_t)row * N + col)       = packhf(v0, v1);
                *(unsigned*)(Ch + (size_t)(row + 8) * N + col) = packhf(v2, v3);
            } else {
                if (MODE == 2) {
                    float2 r0 = *(const float2*)(res + (size_t)row * N + col);
                    float2 r1 = *(const float2*)(res + (size_t)(row + 8) * N + col);
                    v0 += r0.x; v1 += r0.y; v2 += r1.x; v3 += r1.y;
                }
                *(float2*)(C + (size_t)row * N + col)       = make_float2(v0, v1);
                *(float2*)(C + (size_t)(row + 8) * N + col) = make_float2(v2, v3);
            }
        }
    }
}

// ============================================================================
// Flash attention, register softmax, fp16 mma, key tile 64.
// 4 warps x 32 q-rows (m-blocked), cp.async double-buffer.
// SMEM: KV buf0 @0 (K 9216 | V 9216), buf1 @18432, Q @36864..55296
// ============================================================================
#define ALD 144
#define APLANE 9216
#define AKVBUF 18432
#define AQ 36864
#define ATTN_SMEM 55296

__global__ __launch_bounds__(128, 2) void fattn_kernel(
    const __half* __restrict__ Qf, const __half* __restrict__ Kf,
    const __half* __restrict__ Vf, float* __restrict__ O)
{
    extern __shared__ unsigned char smc[];
    const unsigned sbase = (unsigned)__cvta_generic_to_shared(smc);

    const int tid = threadIdx.x;
    const int w   = tid >> 5;
    const int lane = tid & 31;
    const int bh = blockIdx.y;
    const int qt = blockIdx.x;

    const int lj = lane >> 3, lr = lane & 7;
    const int rowoff = (lj & 1) * 8 + lr;
    const int coloff = (lj >> 1) * 8;

    const size_t qbase  = ((size_t)bh * S_ + qt * 128) * DH_;
    const size_t kvbase = (size_t)bh * S_ * DH_;

    // issue Q: 1024 16B chunks -> 8 per thread
    #pragma unroll
    for (int i = 0; i < 8; i++) {
        int chunk = i * 128 + tid;
        int row = chunk >> 3;
        int c8 = (chunk & 7) * 8;
        const __half* src = Qf + qbase + (size_t)row * DH_ + c8;
        cpa16(sbase + AQ + row * ALD + c8 * 2, src);
    }
    // KV tile 0 (64 keys): 1024 chunks -> 8 per thread
    #pragma unroll
    for (int i = 0; i < 8; i++) {
        int chunk = i * 128 + tid;
        int plane = chunk >> 9;       // 0:K 1:V
        int rem = chunk & 511;
        int row = rem >> 3;
        int c8 = (rem & 7) * 8;
        const __half* src = (plane ? Vf : Kf) + kvbase + (size_t)row * DH_ + c8;
        cpa16(sbase + plane * APLANE + row * ALD + c8 * 2, src);
    }
    cpa_commit();

    unsigned qf[2][4][4];
    float oacc[2][8][4];
    #pragma unroll
    for (int mt = 0; mt < 2; mt++)
        #pragma unroll
        for (int t = 0; t < 8; t++) {
            oacc[mt][t][0] = 0.f; oacc[mt][t][1] = 0.f;
            oacc[mt][t][2] = 0.f; oacc[mt][t][3] = 0.f;
        }
    float lsum[2][2];
    lsum[0][0] = 0.f; lsum[0][1] = 0.f; lsum[1][0] = 0.f; lsum[1][1] = 0.f;

    const int NT = S_ / 64;
    for (int kt = 0; kt < NT; kt++) {
        cpa_wait0();
        __syncthreads();

        if (kt == 0) {
            #pragma unroll
            for (int mt = 0; mt < 2; mt++)
                #pragma unroll
                for (int ks = 0; ks < 4; ks++) {
                    unsigned qoff = (unsigned)((w * 32 + mt * 16 + rowoff) * ALD
                                               + (ks * 16 + coloff) * 2);
                    ldsm4(qf[mt][ks], sbase + AQ + qoff);
                }
        }

        const unsigned buf = sbase + (kt & 1) * AKVBUF;

        if (kt + 1 < NT) {
            const size_t tb = kvbase + (size_t)(kt + 1) * 64 * DH_;
            const unsigned dbuf = sbase + ((kt + 1) & 1) * AKVBUF;
            #pragma unroll
            for (int i = 0; i < 8; i++) {
                int chunk = i * 128 + tid;
                int plane = chunk >> 9;
                int rem = chunk & 511;
                int row = rem >> 3;
                int c8 = (rem & 7) * 8;
                const __half* src = (plane ? Vf : Kf) + tb + (size_t)row * DH_ + c8;
                cpa16(dbuf + plane * APLANE + row * ALD + c8 * 2, src);
            }
            cpa_commit();
        }

        // ---- S = Q @ K^T (32 q x 64 keys per warp) ----
        float sacc[2][8][4];
        #pragma unroll
        for (int mt = 0; mt < 2; mt++)
            #pragma unroll
            for (int nt = 0; nt < 8; nt++) {
                sacc[mt][nt][0] = 0.f; sacc[mt][nt][1] = 0.f;
                sacc[mt][nt][2] = 0.f; sacc[mt][nt][3] = 0.f;
            }
        #pragma unroll
        for (int ks = 0; ks < 4; ks++) {
            #pragma unroll
            for (int g2 = 0; g2 < 4; g2++) {
                unsigned kb[4];
                unsigned off = buf + (unsigned)((g2 * 16 + rowoff) * ALD + (ks * 16 + coloff) * 2);
                ldsm4(kb, off);
                #pragma unroll
                for (int mt = 0; mt < 2; mt++) {
                    mma_f16(sacc[mt][2 * g2],     qf[mt][ks], kb[0], kb[2]);
                    mma_f16(sacc[mt][2 * g2 + 1], qf[mt][ks], kb[1], kb[3]);
                }
            }
        }

        // ---- exp in registers (no max needed: |logit| bounded) ----
        #pragma unroll
        for (int mt = 0; mt < 2; mt++)
            #pragma unroll
            for (int nt = 0; nt < 8; nt++) {
                sacc[mt][nt][0] = __expf(sacc[mt][nt][0]); lsum[mt][0] += sacc[mt][nt][0];
                sacc[mt][nt][1] = __expf(sacc[mt][nt][1]); lsum[mt][0] += sacc[mt][nt][1];
                sacc[mt][nt][2] = __expf(sacc[mt][nt][2]); lsum[mt][1] += sacc[mt][nt][2];
                sacc[mt][nt][3] = __expf(sacc[mt][nt][3]); lsum[mt][1] += sacc[mt][nt][3];
            }

        // ---- O += P @ V (64-key k-dim = 4 k16 steps) ----
        #pragma unroll
        for (int ks2 = 0; ks2 < 4; ks2++) {
            unsigned ap[2][4];
            #pragma unroll
            for (int mt = 0; mt < 2; mt++) {
                const float* t0 = sacc[mt][2 * ks2];
                const float* t1 = sacc[mt][2 * ks2 + 1];
                ap[mt][0] = packhf(t0[0], t0[1]);
                ap[mt][1] = packhf(t0[2], t0[3]);
                ap[mt][2] = packhf(t1[0], t1[1]);
                ap[mt][3] = packhf(t1[2], t1[3]);
            }
            #pragma unroll
            for (int gv = 0; gv < 4; gv++) {
                unsigned vb[4];
                unsigned off = buf + APLANE
                             + (unsigned)((ks2 * 16 + rowoff) * ALD + (gv * 16 + coloff) * 2);
                ldsm4t(vb, off);
                #pragma unroll
                for (int mt = 0; mt < 2; mt++) {
                    mma_f16(oacc[mt][2 * gv],     ap[mt], vb[0], vb[1]);
                    mma_f16(oacc[mt][2 * gv + 1], ap[mt], vb[2], vb[3]);
                }
            }
        }
    }

    #pragma unroll
    for (int mt = 0; mt < 2; mt++) {
        lsum[mt][0] += __shfl_xor_sync(0xffffffffu, lsum[mt][0], 1);
        lsum[mt][0] += __shfl_xor_sync(0xffffffffu, lsum[mt][0], 2);
        lsum[mt][1] += __shfl_xor_sync(0xffffffffu, lsum[mt][1], 1);
        lsum[mt][1] += __shfl_xor_sync(0xffffffffu, lsum[mt][1], 2);
    }

    const int b = bh >> 4, h = bh & 15;
    const int g = lane >> 2, c2 = (lane & 3) * 2;
    #pragma unroll
    for (int mt = 0; mt < 2; mt++) {
        const float inv0 = 1.f / lsum[mt][0];
        const float inv1 = 1.f / lsum[mt][1];
        const int r0 = qt * 128 + w * 32 + mt * 16 + g;
        float* o0 = O + ((size_t)(b * S_) + r0) * D_ + h * DH_;
        float* o1 = o0 + (size_t)8 * D_;
        #pragma unroll
        for (int t = 0; t < 8; t++) {
            *(float2*)(o0 + t * 8 + c2) =
                make_float2(oacc[mt][t][0] * inv0, oacc[mt][t][1] * inv0);
            *(float2*)(o1 + t * 8 + c2) =
                make_float2(oacc[mt][t][2] * inv1, oacc[mt][t][3] * inv1);
        }
    }
}

// ---------------- QKV transform: l2norm + scale + xpos rotary ---------------
__global__ __launch_bounds__(256) void transform_kernel(
    const float* __restrict__ qkv,
    const float* __restrict__ q_scale, const float* __restrict__ k_scale,
    __half* __restrict__ Qf, __half* __restrict__ Kf, __half* __restrict__ Vf)
{
    const int gw   = (blockIdx.x * blockDim.x + threadIdx.x) >> 5;
    const int lane = threadIdx.x & 31;
    const int s  = gw & (S_ - 1);
    const int bh = gw >> 11;
    if (bh >= BH_) return;
    const int b = bh >> 4, h = bh & 15;

    const float* base = qkv + ((size_t)(b * S_ + s)) * (3 * D_) + h * (3 * DH_);
    float q0 = base[lane],       q1 = base[lane + 32];
    float k0 = base[64 + lane],  k1 = base[96 + lane];
    float v0 = base[128 + lane], v1 = base[160 + lane];

    float nq = q0 * q0 + q1 * q1;
    float nk = k0 * k0 + k1 * k1;
    #pragma unroll
    for (int off = 16; off; off >>= 1) {
        nq += __shfl_xor_sync(0xffffffffu, nq, off);
        nk += __shfl_xor_sync(0xffffffffu, nk, off);
    }
    nq = fmaxf(sqrtf(nq), 1e-12f);
    nk = fmaxf(sqrtf(nk), 1e-12f);

    q0 = q0 / nq * q_scale[lane]; q1 = q1 / nq * q_scale[lane + 32];
    k0 = k0 / nk * k_scale[lane]; k1 = k1 / nk * k_scale[lane + 32];

    const float d2 = 2.0f * (float)lane;
    const float inv_freq = exp2f(-d2 * (13.287712379549449f / 64.0f));
    const float fr = (float)s * inv_freq;
    float sn, c;
    sincosf(fr, &sn, &c);

    const float basev = (d2 + 0.4f * 64.0f) / (1.4f * 64.0f);
    const float power = ((float)s - (float)(S_ / 2)) / 512.0f;
    const float scale = exp2f(power * log2f(basev));
    const float iscale = 1.0f / scale;

    const float qo0 = (q0 * c - q1 * sn) * scale * 0.125f;
    const float qo1 = (q1 * c + q0 * sn) * scale * 0.125f;
    const float ko0 = (k0 * c - k1 * sn) * iscale;
    const float ko1 = (k1 * c + k0 * sn) * iscale;

    const size_t ob = ((size_t)bh * S_ + s) * DH_;
    Qf[ob + lane]      = __float2half_rn(qo0);
    Qf[ob + lane + 32] = __float2half_rn(qo1);
    Kf[ob + lane]      = __float2half_rn(ko0);
    Kf[ob + lane + 32] = __float2half_rn(ko1);
    Vf[ob + lane]      = __float2half_rn(v0);
    Vf[ob + lane + 32] = __float2half_rn(v1);
}

// ---------------- LayerNorm (emits fp32 + fp16 plane) ------------------------
__global__ __launch_bounds__(256) void ln_kernel(
    const float* __restrict__ X, const float* __restrict__ g,
    const float* __restrict__ bb, float* __restrict__ Y,
    __half* __restrict__ Yh)
{
    __shared__ float red[16];
    const int row = blockIdx.x;
    const int tid = threadIdx.x;
    const float* xp = X + (size_t)row * D_;

    float4 x4 = ((const float4*)xp)[tid];
    float s  = x4.x + x4.y + x4.z + x4.w;
    float ss = x4.x * x4.x + x4.y * x4.y + x4.z * x4.z + x4.w * x4.w;

    #pragma unroll
    for (int off = 16; off; off >>= 1) {
        s  += __shfl_xor_sync(0xffffffffu, s,  off);
        ss += __shfl_xor_sync(0xffffffffu, ss, off);
    }
    const int wid = tid >> 5, lane = tid & 31;
    if (lane == 0) { red[wid] = s; red[wid + 8] = ss; }
    __syncthreads();
    if (wid == 0) {
        float a = (lane < 8) ? red[lane] : 0.f;
        float bsum = (lane < 8) ? red[lane + 8] : 0.f;
        #pragma unroll
        for (int off = 4; off; off >>= 1) {
            a    += __shfl_xor_sync(0xffffffffu, a,    off);
            bsum += __shfl_xor_sync(0xffffffffu, bsum, off);
        }
        if (lane == 0) { red[0] = a; red[1] = bsum; }
    }
    __syncthreads();
    const float mu  = red[0] * (1.0f / D_);
    const float var = red[1] * (1.0f / D_) - mu * mu;
    const float rstd = rsqrtf(var + 1e-5f);

    float4 g4 = ((const float4*)g)[tid];
    float4 b4 = ((const float4*)bb)[tid];
    float4 y;
    y.x = (x4.x - mu) * rstd * g4.x + b4.x;
    y.y = (x4.y - mu) * rstd * g4.y + b4.y;
    y.z = (x4.z - mu) * rstd * g4.z + b4.z;
    y.w = (x4.w - mu) * rstd * g4.w + b4.w;
    ((float4*)(Y + (size_t)row * D_))[tid] = y;
    ((uint2*)(Yh + (size_t)row * D_))[tid] =
        make_uint2(packhf(y.x, y.y), packhf(y.z, y.w));
}

// ---------------- launch -----------------------------------------------------
extern "C" void kernel_launch(void* const* d_in, const int* in_sizes, int n_in,
                              void* d_out, int out_size)
{
    const float* Q     = (const float*)d_in[0];
    const float* Wqkv  = (const float*)d_in[3];
    const float* bqkv  = (const float*)d_in[4];
    const float* q_sc  = (const float*)d_in[5];
    const float* k_sc  = (const float*)d_in[6];
    const float* ln_g  = (const float*)d_in[7];
    const float* ln_b  = (const float*)d_in[8];
    const float* W1    = (const float*)d_in[9];
    const float* b1    = (const float*)d_in[10];
    const float* W2    = (const float*)d_in[11];
    const float* b2    = (const float*)d_in[12];
    float* out = (float*)d_out;

    float *qkv, *att, *x;
    __half *qi, *wq, *w1, *w2, *qf, *kf, *vf, *xh, *hh;
    cudaGetSymbolAddress((void**)&qkv, g_qkv);
    cudaGetSymbolAddress((void**)&qi,  g_qi);
    cudaGetSymbolAddress((void**)&wq,  g_wq);
    cudaGetSymbolAddress((void**)&w1,  g_w1);
    cudaGetSymbolAddress((void**)&w2,  g_w2);
    cudaGetSymbolAddress((void**)&qf,  g_qf);
    cudaGetSymbolAddress((void**)&kf,  g_kf);
    cudaGetSymbolAddress((void**)&vf,  g_vf);
    cudaGetSymbolAddress((void**)&att, g_att);
    cudaGetSymbolAddress((void**)&x,   g_x);
    cudaGetSymbolAddress((void**)&xh,  g_xh);
    cudaGetSymbolAddress((void**)&hh,  g_hh);

    cudaFuncSetAttribute(fattn_kernel,
                         cudaFuncAttributeMaxDynamicSharedMemorySize, ATTN_SMEM);
    cudaFuncSetAttribute(mma_gemm<0>,
                         cudaFuncAttributeMaxDynamicSharedMemorySize, GEMM_SMEM);
    cudaFuncSetAttribute(mma_gemm<1>,
                         cudaFuncAttributeMaxDynamicSharedMemorySize, GEMM_SMEM);
    cudaFuncSetAttribute(mma_gemm<2>,
                         cudaFuncAttributeMaxDynamicSharedMemorySize, GEMM_SMEM);

    // 0) convert input + all weights to fp16 in ONE launch
    hsplit_all<<<2048, 256>>>(
        Q,    qi, BS_ * D_ / 4,
        Wqkv, wq, D_ * 3 * D_ / 4,
        W1,   w1, D_ * FF_ / 4,
        W2,   w2, FF_ * D_ / 4);

    // 1) QKV projection
    mma_gemm<0><<<dim3(3 * D_ / 128, BS_ / 128), 128, GEMM_SMEM>>>(
        qi, wq, bqkv, nullptr, qkv, nullptr, BS_, 3 * D_, D_);

    // 2) l2norm + scale + rotary -> fp16 q/k/v
    transform_kernel<<<BH_ * S_ / 8, 256>>>(qkv, q_sc, k_sc, qf, kf, vf);

    // 3) flash attention (key tile 64)
    fattn_kernel<<<dim3(S_ / 128, BH_), 128, ATTN_SMEM>>>(qf, kf, vf, att);

    // 4) LayerNorm -> x fp32 + fp16 plane
    ln_kernel<<<BS_, 256>>>(att, ln_g, ln_b, x, xh);

    // 5) FF1 + SiLU -> h fp16
    mma_gemm<1><<<dim3(FF_ / 128, BS_ / 128), 128, GEMM_SMEM>>>(
        xh, w1, b1, nullptr, nullptr, hh, BS_, FF_, D_);

    // 6) FF2 + residual -> out fp32
    mma_gemm<2><<<dim3(D_ / 128, BS_ / 128), 128, GEMM_SMEM>>>(
        hh, w2, b2, x, out, nullptr, BS_, D_, FF_);
}

// round 17
// speedup vs baseline: 1.0344x; 1.0344x over previous
#include <cuda_runtime.h>
#include <cuda_bf16.h>
#include <cuda_fp16.h>
#include <math.h>
#include <stdint.h>

#define B_   4
#define S_   2048
#define H_   16
#define DH_  64
#define D_   1024
#define FF_  2048
#define BS_  (B_*S_)
#define BH_  (B_*H_)

// ---------------- scratch (device globals; no runtime allocation) -----------
__device__ float  g_qkv[(size_t)BS_ * 3 * D_];
__device__ __half g_qi [(size_t)BS_ * D_];
__device__ __half g_wq [(size_t)D_ * 3 * D_];
__device__ __half g_w1 [(size_t)D_ * FF_];
__device__ __half g_w2 [(size_t)FF_ * D_];
__device__ __half g_qf [(size_t)BH_ * S_ * DH_];
__device__ __half g_kf [(size_t)BH_ * S_ * DH_];
__device__ __half g_vf [(size_t)BH_ * S_ * DH_];
__device__ float  g_att[(size_t)BS_ * D_];
__device__ float  g_x  [(size_t)BS_ * D_];
__device__ __half g_xh [(size_t)BS_ * D_];
__device__ __half g_hh [(size_t)BS_ * FF_];

// ---------------- helpers ------------------------------------------------------
__device__ __forceinline__ unsigned packhf(float a, float b) {
    __half2 t = __floats2half2_rn(a, b);
    return *reinterpret_cast<unsigned*>(&t);
}

// ---------------- PTX primitives ---------------------------------------------
__device__ __forceinline__ void ldsm4(unsigned* d, unsigned a) {
    asm volatile("ldmatrix.sync.aligned.m8n8.x4.shared.b16 {%0,%1,%2,%3}, [%4];"
                 : "=r"(d[0]), "=r"(d[1]), "=r"(d[2]), "=r"(d[3]) : "r"(a));
}
__device__ __forceinline__ void ldsm4t(unsigned* d, unsigned a) {
    asm volatile("ldmatrix.sync.aligned.m8n8.x4.trans.shared.b16 {%0,%1,%2,%3}, [%4];"
                 : "=r"(d[0]), "=r"(d[1]), "=r"(d[2]), "=r"(d[3]) : "r"(a));
}
__device__ __forceinline__ void mma_f16(float* c, const unsigned* a,
                                        unsigned b0, unsigned b1) {
    asm volatile(
        "mma.sync.aligned.m16n8k16.row.col.f32.f16.f16.f32 "
        "{%0,%1,%2,%3}, {%4,%5,%6,%7}, {%8,%9}, {%0,%1,%2,%3};"
        : "+f"(c[0]), "+f"(c[1]), "+f"(c[2]), "+f"(c[3])
        : "r"(a[0]), "r"(a[1]), "r"(a[2]), "r"(a[3]), "r"(b0), "r"(b1));
}
__device__ __forceinline__ void cpa16(unsigned dst, const void* src) {
    asm volatile("cp.async.ca.shared.global [%0], [%1], 16;" :: "r"(dst), "l"(src));
}
__device__ __forceinline__ void cpa_commit() {
    asm volatile("cp.async.commit_group;");
}
__device__ __forceinline__ void cpa_wait0() {
    asm volatile("cp.async.wait_group 0;" ::: "memory");
}

// ============================================================================
// fused convert: all fp32->fp16 planes in one launch
// ============================================================================
__global__ __launch_bounds__(256) void hsplit_all(
    const float* __restrict__ A0, __half* __restrict__ O0, int n0,
    const float* __restrict__ A1, __half* __restrict__ O1, int n1,
    const float* __restrict__ A2, __half* __restrict__ O2, int n2,
    const float* __restrict__ A3, __half* __restrict__ O3, int n3)
{
    const int stride = gridDim.x * blockDim.x;
    const int total = n0 + n1 + n2 + n3;
    for (int i = blockIdx.x * blockDim.x + threadIdx.x; i < total; i += stride) {
        const float* src;
        __half* dst;
        int j = i;
        if (j < n0) { src = A0; dst = O0; }
        else if ((j -= n0) < n1) { src = A1; dst = O1; }
        else if ((j -= n1) < n2) { src = A2; dst = O2; }
        else { j -= n2; src = A3; dst = O3; }
        float4 v = ((const float4*)src)[j];
        ((uint2*)dst)[j] = make_uint2(packhf(v.x, v.y), packhf(v.z, v.w));
    }
}

// ============================================================================
// Raw-mma fp16 GEMM, k-chunk 64, cp.async double-buffer, 1 sync/chunk.
// CTA 128x128, 4 warps (2m x 2n), warp tile 64x64. Algebraic staging addrs.
// MODE 0: C fp32.  MODE 1: SiLU -> Ch fp16.  MODE 2: +res -> C fp32.
// Buffer: A[128][72h] 18432 B | B[64][136h] 17408 B => 35840/buffer.
// ============================================================================
#define GA_ 144
#define GB_ 272
#define GBUF 35840
#define GEMM_SMEM (2 * GBUF)

template <int MODE>
__global__ __launch_bounds__(128, 2) void mma_gemm(
    const __half* __restrict__ Ah, const __half* __restrict__ Bh,
    const float* __restrict__ bias, const float* __restrict__ res,
    float* __restrict__ C, __half* __restrict__ Ch,
    int M, int N, int K)
{
    extern __shared__ unsigned char smg[];
    const unsigned sb = (unsigned)__cvta_generic_to_shared(smg);

    const int tid = threadIdx.x;
    const int w = tid >> 5;
    const int lane = tid & 31;
    const int wmr = w >> 1;
    const int wnc = w & 1;
    const int bx = blockIdx.x, by = blockIdx.y;

    const int lj = lane >> 3, lr = lane & 7;
    const int rowoff = (lj & 1) * 8 + lr;
    const int coloff = (lj >> 1) * 8;
    const int g = lane >> 2, c2 = (lane & 3) * 2;

    float acc[4][8][4];
    #pragma unroll
    for (int mt = 0; mt < 4; mt++)
        #pragma unroll
        for (int n = 0; n < 8; n++) {
            acc[mt][n][0] = 0.f; acc[mt][n][1] = 0.f;
            acc[mt][n][2] = 0.f; acc[mt][n][3] = 0.f;
        }

    const int NC = K >> 6;

    // algebraic staging bases (per thread, constant across tiles)
    const int ar0 = tid >> 3;            // A row base (rows += 16/iter)
    const int ac8 = (tid & 7) * 8;       // A col (halves)
    const int br0 = tid >> 4;            // B row base (rows += 8/iter)
    const int bo8 = (tid & 15) * 8;      // B col (halves)
    const __half* agp = Ah + (size_t)(by * 128 + ar0) * K + ac8;
    const __half* bgp = Bh + (size_t)br0 * N + bx * 128 + bo8;
    const unsigned adst0 = ar0 * GA_ + ac8 * 2;
    const unsigned bdst0 = 18432u + br0 * GB_ + bo8 * 2;

    auto stage = [&](int kc, unsigned bufo) {
        const int k0 = kc * 64;
        #pragma unroll
        for (int j = 0; j < 8; j++)
            cpa16(sb + bufo + adst0 + j * (16 * GA_),
                  agp + (size_t)(j * 16) * K + k0);
        #pragma unroll
        for (int j = 0; j < 8; j++)
            cpa16(sb + bufo + bdst0 + j * (8 * GB_),
                  bgp + (size_t)(k0 + j * 8) * N);
    };

    stage(0, 0u);
    cpa_commit();

    for (int kc = 0; kc < NC; kc++) {
        cpa_wait0();
        __syncthreads();

        const unsigned buf = (unsigned)((kc & 1) * GBUF);
        if (kc + 1 < NC) {
            stage(kc + 1, (unsigned)(((kc + 1) & 1) * GBUF));
            cpa_commit();
        }

        const unsigned uA = sb + buf, uB = sb + buf + 18432u;

        #pragma unroll
        for (int ks = 0; ks < 4; ks++) {
            unsigned ah[4][4];
            #pragma unroll
            for (int mt = 0; mt < 4; mt++) {
                const unsigned addr = uA
                    + (unsigned)((wmr * 64 + mt * 16 + rowoff) * GA_ + (ks * 16 + coloff) * 2);
                ldsm4(ah[mt], addr);
            }
            #pragma unroll
            for (int gg = 0; gg < 4; gg++) {
                unsigned bf[4];
                const unsigned baddr = uB
                    + (unsigned)((ks * 16 + rowoff) * GB_ + (wnc * 64 + gg * 16 + coloff) * 2);
                ldsm4t(bf, baddr);
                #pragma unroll
                for (int mt = 0; mt < 4; mt++) {
                    mma_f16(acc[mt][2 * gg],     ah[mt], bf[0], bf[1]);
                    mma_f16(acc[mt][2 * gg + 1], ah[mt], bf[2], bf[3]);
                }
            }
        }
    }

    #pragma unroll
    for (int mt = 0; mt < 4; mt++) {
        #pragma unroll
        for (int n = 0; n < 8; n++) {
            const int row = by * 128 + wmr * 64 + mt * 16 + g;
            const int col = bx * 128 + wnc * 64 + n * 8 + c2;
            float2 bb2 = *(const float2*)(bias + col);
            float v0 = acc[mt][n][0] + bb2.x;
            float v1 = acc[mt][n][1] + bb2.y;
            float v2 = acc[mt][n][2] + bb2.x;
            float v3 = acc[mt][n][3] + bb2.y;
            if (MODE == 1) {
                v0 = v0 / (1.f + __expf(-v0));
                v1 = v1 / (1.f + __expf(-v1));
                v2 = v2 / (1.f + __expf(-v2));
                v3 = v3 / (1.f + __expf(-v3));
                *(unsigned*)(Ch + (size_t)row * N + col)       = packhf(v0, v1);
                *(unsigned*)(Ch + (size_t)(row + 8) * N + col) = packhf(v2, v3);
            } else {
                if (MODE == 2) {
                    float2 r0 = *(const float2*)(res + (size_t)row * N + col);
                    float2 r1 = *(const float2*)(res + (size_t)(row + 8) * N + col);
                    v0 += r0.x; v1 += r0.y; v2 += r1.x; v3 += r1.y;
                }
                *(float2*)(C + (size_t)row * N + col)       = make_float2(v0, v1);
                *(float2*)(C + (size_t)(row + 8) * N + col) = make_float2(v2, v3);
            }
        }
    }
}

// ============================================================================
// Flash attention, register softmax (exp2, log2e pre-folded into Q),
// fp16 mma, key tile 64, algebraic staging addresses.
// SMEM: KV buf0 @0 (K 9216 | V 9216), buf1 @18432, Q @36864..55296
// ============================================================================
#define ALD 144
#define APLANE 9216
#define AKVBUF 18432
#define AQ 36864
#define ATTN_SMEM 55296

__global__ __launch_bounds__(128, 2) void fattn_kernel(
    const __half* __restrict__ Qf, const __half* __restrict__ Kf,
    const __half* __restrict__ Vf, float* __restrict__ O)
{
    extern __shared__ unsigned char smc[];
    const unsigned sbase = (unsigned)__cvta_generic_to_shared(smc);

    const int tid = threadIdx.x;
    const int w   = tid >> 5;
    const int lane = tid & 31;
    const int bh = blockIdx.y;
    const int qt = blockIdx.x;

    const int lj = lane >> 3, lr = lane & 7;
    const int rowoff = (lj & 1) * 8 + lr;
    const int coloff = (lj >> 1) * 8;

    const size_t qbase  = ((size_t)bh * S_ + qt * 128) * DH_;
    const size_t kvbase = (size_t)bh * S_ * DH_;

    // algebraic staging bases
    const int sr0 = tid >> 3;            // row base (rows += 16/iter)
    const int sc8 = (tid & 7) * 8;       // col (halves)
    const unsigned kvdst0 = sr0 * ALD + sc8 * 2;
    const __half* kgp = Kf + kvbase + (size_t)sr0 * DH_ + sc8;
    const __half* vgp = Vf + kvbase + (size_t)sr0 * DH_ + sc8;

    // issue Q: rows sr0 + j*16, j=0..7
    {
        const __half* qgp = Qf + qbase + (size_t)sr0 * DH_ + sc8;
        #pragma unroll
        for (int j = 0; j < 8; j++)
            cpa16(sbase + AQ + kvdst0 + j * (16 * ALD), qgp + j * 16 * DH_);
    }
    // KV tile 0: K rows j=0..3, V rows j=0..3
    #pragma unroll
    for (int j = 0; j < 4; j++)
        cpa16(sbase + kvdst0 + j * (16 * ALD), kgp + j * 16 * DH_);
    #pragma unroll
    for (int j = 0; j < 4; j++)
        cpa16(sbase + APLANE + kvdst0 + j * (16 * ALD), vgp + j * 16 * DH_);
    cpa_commit();

    unsigned qf[2][4][4];
    float oacc[2][8][4];
    #pragma unroll
    for (int mt = 0; mt < 2; mt++)
        #pragma unroll
        for (int t = 0; t < 8; t++) {
            oacc[mt][t][0] = 0.f; oacc[mt][t][1] = 0.f;
            oacc[mt][t][2] = 0.f; oacc[mt][t][3] = 0.f;
        }
    float lsum[2][2];
    lsum[0][0] = 0.f; lsum[0][1] = 0.f; lsum[1][0] = 0.f; lsum[1][1] = 0.f;

    const int NT = S_ / 64;
    for (int kt = 0; kt < NT; kt++) {
        cpa_wait0();
        __syncthreads();

        if (kt == 0) {
            #pragma unroll
            for (int mt = 0; mt < 2; mt++)
                #pragma unroll
                for (int ks = 0; ks < 4; ks++) {
                    unsigned qoff = (unsigned)((w * 32 + mt * 16 + rowoff) * ALD
                                               + (ks * 16 + coloff) * 2);
                    ldsm4(qf[mt][ks], sbase + AQ + qoff);
                }
        }

        const unsigned buf = sbase + (kt & 1) * AKVBUF;

        if (kt + 1 < NT) {
            const size_t adv = (size_t)(kt + 1) * 64 * DH_;
            const unsigned dbuf = sbase + ((kt + 1) & 1) * AKVBUF;
            #pragma unroll
            for (int j = 0; j < 4; j++)
                cpa16(dbuf + kvdst0 + j * (16 * ALD), kgp + adv + j * 16 * DH_);
            #pragma unroll
            for (int j = 0; j < 4; j++)
                cpa16(dbuf + APLANE + kvdst0 + j * (16 * ALD), vgp + adv + j * 16 * DH_);
            cpa_commit();
        }

        // ---- S = Q @ K^T (32 q x 64 keys per warp) ----
        float sacc[2][8][4];
        #pragma unroll
        for (int mt = 0; mt < 2; mt++)
            #pragma unroll
            for (int nt = 0; nt < 8; nt++) {
                sacc[mt][nt][0] = 0.f; sacc[mt][nt][1] = 0.f;
                sacc[mt][nt][2] = 0.f; sacc[mt][nt][3] = 0.f;
            }
        #pragma unroll
        for (int ks = 0; ks < 4; ks++) {
            #pragma unroll
            for (int g2 = 0; g2 < 4; g2++) {
                unsigned kb[4];
                unsigned off = buf + (unsigned)((g2 * 16 + rowoff) * ALD + (ks * 16 + coloff) * 2);
                ldsm4(kb, off);
                #pragma unroll
                for (int mt = 0; mt < 2; mt++) {
                    mma_f16(sacc[mt][2 * g2],     qf[mt][ks], kb[0], kb[2]);
                    mma_f16(sacc[mt][2 * g2 + 1], qf[mt][ks], kb[1], kb[3]);
                }
            }
        }

        // ---- exp2 in registers (log2e pre-folded into Q) ----
        #pragma unroll
        for (int mt = 0; mt < 2; mt++)
            #pragma unroll
            for (int nt = 0; nt < 8; nt++) {
                sacc[mt][nt][0] = exp2f(sacc[mt][nt][0]); lsum[mt][0] += sacc[mt][nt][0];
                sacc[mt][nt][1] = exp2f(sacc[mt][nt][1]); lsum[mt][0] += sacc[mt][nt][1];
                sacc[mt][nt][2] = exp2f(sacc[mt][nt][2]); lsum[mt][1] += sacc[mt][nt][2];
                sacc[mt][nt][3] = exp2f(sacc[mt][nt][3]); lsum[mt][1] += sacc[mt][nt][3];
            }

        // ---- O += P @ V ----
        #pragma unroll
        for (int ks2 = 0; ks2 < 4; ks2++) {
            unsigned ap[2][4];
            #pragma unroll
            for (int mt = 0; mt < 2; mt++) {
                const float* t0 = sacc[mt][2 * ks2];
                const float* t1 = sacc[mt][2 * ks2 + 1];
                ap[mt][0] = packhf(t0[0], t0[1]);
                ap[mt][1] = packhf(t0[2], t0[3]);
                ap[mt][2] = packhf(t1[0], t1[1]);
                ap[mt][3] = packhf(t1[2], t1[3]);
            }
            #pragma unroll
            for (int gv = 0; gv < 4; gv++) {
                unsigned vb[4];
                unsigned off = buf + APLANE
                             + (unsigned)((ks2 * 16 + rowoff) * ALD + (gv * 16 + coloff) * 2);
                ldsm4t(vb, off);
                #pragma unroll
                for (int mt = 0; mt < 2; mt++) {
                    mma_f16(oacc[mt][2 * gv],     ap[mt], vb[0], vb[1]);
                    mma_f16(oacc[mt][2 * gv + 1], ap[mt], vb[2], vb[3]);
                }
            }
        }
    }

    #pragma unroll
    for (int mt = 0; mt < 2; mt++) {
        lsum[mt][0] += __shfl_xor_sync(0xffffffffu, lsum[mt][0], 1);
        lsum[mt][0] += __shfl_xor_sync(0xffffffffu, lsum[mt][0], 2);
        lsum[mt][1] += __shfl_xor_sync(0xffffffffu, lsum[mt][1], 1);
        lsum[mt][1] += __shfl_xor_sync(0xffffffffu, lsum[mt][1], 2);
    }

    const int b = bh >> 4, h = bh & 15;
    const int g = lane >> 2, c2 = (lane & 3) * 2;
    #pragma unroll
    for (int mt = 0; mt < 2; mt++) {
        const float inv0 = 1.f / lsum[mt][0];
        const float inv1 = 1.f / lsum[mt][1];
        const int r0 = qt * 128 + w * 32 + mt * 16 + g;
        float* o0 = O + ((size_t)(b * S_) + r0) * D_ + h * DH_;
        float* o1 = o0 + (size_t)8 * D_;
        #pragma unroll
        for (int t = 0; t < 8; t++) {
            *(float2*)(o0 + t * 8 + c2) =
                make_float2(oacc[mt][t][0] * inv0, oacc[mt][t][1] * inv0);
            *(float2*)(o1 + t * 8 + c2) =
                make_float2(oacc[mt][t][2] * inv1, oacc[mt][t][3] * inv1);
        }
    }
}

// ---------------- QKV transform: l2norm + scale + xpos rotary ---------------
// Q pre-scaled by 0.125 * log2(e) so attention can use exp2.
__global__ __launch_bounds__(256) void transform_kernel(
    const float* __restrict__ qkv,
    const float* __restrict__ q_scale, const float* __restrict__ k_scale,
    __half* __restrict__ Qf, __half* __restrict__ Kf, __half* __restrict__ Vf)
{
    const int gw   = (blockIdx.x * blockDim.x + threadIdx.x) >> 5;
    const int lane = threadIdx.x & 31;
    const int s  = gw & (S_ - 1);
    const int bh = gw >> 11;
    if (bh >= BH_) return;
    const int b = bh >> 4, h = bh & 15;

    const float* base = qkv + ((size_t)(b * S_ + s)) * (3 * D_) + h * (3 * DH_);
    float q0 = base[lane],       q1 = base[lane + 32];
    float k0 = base[64 + lane],  k1 = base[96 + lane];
    float v0 = base[128 + lane], v1 = base[160 + lane];

    float nq = q0 * q0 + q1 * q1;
    float nk = k0 * k0 + k1 * k1;
    #pragma unroll
    for (int off = 16; off; off >>= 1) {
        nq += __shfl_xor_sync(0xffffffffu, nq, off);
        nk += __shfl_xor_sync(0xffffffffu, nk, off);
    }
    nq = fmaxf(sqrtf(nq), 1e-12f);
    nk = fmaxf(sqrtf(nk), 1e-12f);

    q0 = q0 / nq * q_scale[lane]; q1 = q1 / nq * q_scale[lane + 32];
    k0 = k0 / nk * k_scale[lane]; k1 = k1 / nk * k_scale[lane + 32];

    const float d2 = 2.0f * (float)lane;
    const float inv_freq = exp2f(-d2 * (13.287712379549449f / 64.0f));
    const float fr = (float)s * inv_freq;
    float sn, c;
    sincosf(fr, &sn, &c);

    const float basev = (d2 + 0.4f * 64.0f) / (1.4f * 64.0f);
    const float power = ((float)s - (float)(S_ / 2)) / 512.0f;
    const float scale = exp2f(power * log2f(basev));
    const float iscale = 1.0f / scale;

    const float QS = 0.125f * 1.4426950408889634f;   // fold log2e for exp2
    const float qo0 = (q0 * c - q1 * sn) * scale * QS;
    const float qo1 = (q1 * c + q0 * sn) * scale * QS;
    const float ko0 = (k0 * c - k1 * sn) * iscale;
    const float ko1 = (k1 * c + k0 * sn) * iscale;

    const size_t ob = ((size_t)bh * S_ + s) * DH_;
    Qf[ob + lane]      = __float2half_rn(qo0);
    Qf[ob + lane + 32] = __float2half_rn(qo1);
    Kf[ob + lane]      = __float2half_rn(ko0);
    Kf[ob + lane + 32] = __float2half_rn(ko1);
    Vf[ob + lane]      = __float2half_rn(v0);
    Vf[ob + lane + 32] = __float2half_rn(v1);
}

// ---------------- LayerNorm (emits fp32 + fp16 plane) ------------------------
__global__ __launch_bounds__(256) void ln_kernel(
    const float* __restrict__ X, const float* __restrict__ g,
    const float* __restrict__ bb, float* __restrict__ Y,
    __half* __restrict__ Yh)
{
    __shared__ float red[16];
    const int row = blockIdx.x;
    const int tid = threadIdx.x;
    const float* xp = X + (size_t)row * D_;

    float4 x4 = ((const float4*)xp)[tid];
    float s  = x4.x + x4.y + x4.z + x4.w;
    float ss = x4.x * x4.x + x4.y * x4.y + x4.z * x4.z + x4.w * x4.w;

    #pragma unroll
    for (int off = 16; off; off >>= 1) {
        s  += __shfl_xor_sync(0xffffffffu, s,  off);
        ss += __shfl_xor_sync(0xffffffffu, ss, off);
    }
    const int wid = tid >> 5, lane = tid & 31;
    if (lane == 0) { red[wid] = s; red[wid + 8] = ss; }
    __syncthreads();
    if (wid == 0) {
        float a = (lane < 8) ? red[lane] : 0.f;
        float bsum = (lane < 8) ? red[lane + 8] : 0.f;
        #pragma unroll
        for (int off = 4; off; off >>= 1) {
            a    += __shfl_xor_sync(0xffffffffu, a,    off);
            bsum += __shfl_xor_sync(0xffffffffu, bsum, off);
        }
        if (lane == 0) { red[0] = a; red[1] = bsum; }
    }
    __syncthreads();
    const float mu  = red[0] * (1.0f / D_);
    const float var = red[1] * (1.0f / D_) - mu * mu;
    const float rstd = rsqrtf(var + 1e-5f);

    float4 g4 = ((const float4*)g)[tid];
    float4 b4 = ((const float4*)bb)[tid];
    float4 y;
    y.x = (x4.x - mu) * rstd * g4.x + b4.x;
    y.y = (x4.y - mu) * rstd * g4.y + b4.y;
    y.z = (x4.z - mu) * rstd * g4.z + b4.z;
    y.w = (x4.w - mu) * rstd * g4.w + b4.w;
    ((float4*)(Y + (size_t)row * D_))[tid] = y;
    ((uint2*)(Yh + (size_t)row * D_))[tid] =
        make_uint2(packhf(y.x, y.y), packhf(y.z, y.w));
}

// ---------------- launch -----------------------------------------------------
extern "C" void kernel_launch(void* const* d_in, const int* in_sizes, int n_in,
                              void* d_out, int out_size)
{
    const float* Q     = (const float*)d_in[0];
    const float* Wqkv  = (const float*)d_in[3];
    const float* bqkv  = (const float*)d_in[4];
    const float* q_sc  = (const float*)d_in[5];
    const float* k_sc  = (const float*)d_in[6];
    const float* ln_g  = (const float*)d_in[7];
    const float* ln_b  = (const float*)d_in[8];
    const float* W1    = (const float*)d_in[9];
    const float* b1    = (const float*)d_in[10];
    const float* W2    = (const float*)d_in[11];
    const float* b2    = (const float*)d_in[12];
    float* out = (float*)d_out;

    float *qkv, *att, *x;
    __half *qi, *wq, *w1, *w2, *qf, *kf, *vf, *xh, *hh;
    cudaGetSymbolAddress((void**)&qkv, g_qkv);
    cudaGetSymbolAddress((void**)&qi,  g_qi);
    cudaGetSymbolAddress((void**)&wq,  g_wq);
    cudaGetSymbolAddress((void**)&w1,  g_w1);
    cudaGetSymbolAddress((void**)&w2,  g_w2);
    cudaGetSymbolAddress((void**)&qf,  g_qf);
    cudaGetSymbolAddress((void**)&kf,  g_kf);
    cudaGetSymbolAddress((void**)&vf,  g_vf);
    cudaGetSymbolAddress((void**)&att, g_att);
    cudaGetSymbolAddress((void**)&x,   g_x);
    cudaGetSymbolAddress((void**)&xh,  g_xh);
    cudaGetSymbolAddress((void**)&hh,  g_hh);

    cudaFuncSetAttribute(fattn_kernel,
                         cudaFuncAttributeMaxDynamicSharedMemorySize, ATTN_SMEM);
    cudaFuncSetAttribute(mma_gemm<0>,
                         cudaFuncAttributeMaxDynamicSharedMemorySize, GEMM_SMEM);
    cudaFuncSetAttribute(mma_gemm<1>,
                         cudaFuncAttributeMaxDynamicSharedMemorySize, GEMM_SMEM);
    cudaFuncSetAttribute(mma_gemm<2>,
                         cudaFuncAttributeMaxDynamicSharedMemorySize, GEMM_SMEM);

    // 0) convert input + all weights to fp16 in one launch
    hsplit_all<<<2048, 256>>>(
        Q,    qi, BS_ * D_ / 4,
        Wqkv, wq, D_ * 3 * D_ / 4,
        W1,   w1, D_ * FF_ / 4,
        W2,   w2, FF_ * D_ / 4);

    // 1) QKV projection
    mma_gemm<0><<<dim3(3 * D_ / 128, BS_ / 128), 128, GEMM_SMEM>>>(
        qi, wq, bqkv, nullptr, qkv, nullptr, BS_, 3 * D_, D_);

    // 2) l2norm + scale + rotary -> fp16 q/k/v (q pre-scaled by log2e)
    transform_kernel<<<BH_ * S_ / 8, 256>>>(qkv, q_sc, k_sc, qf, kf, vf);

    // 3) flash attention
    fattn_kernel<<<dim3(S_ / 128, BH_), 128, ATTN_SMEM>>>(qf, kf, vf, att);

    // 4) LayerNorm -> x fp32 + fp16 plane
    ln_kernel<<<BS_, 256>>>(att, ln_g, ln_b, x, xh);

    // 5) FF1 + SiLU -> h fp16
    mma_gemm<1><<<dim3(FF_ / 128, BS_ / 128), 128, GEMM_SMEM>>>(
        xh, w1, b1, nullptr, nullptr, hh, BS_, FF_, D_);

    // 6) FF2 + residual -> out fp32
    mma_gemm<2><<<dim3(D_ / 128, BS_ / 128), 128, GEMM_SMEM>>>(
        hh, w2, b2, x, out, nullptr, BS_, D_, FF_);
}